// round 11
// baseline (speedup 1.0000x reference)
#include <cuda_runtime.h>
#include <cuda_fp16.h>

// ---------------------------------------------------------------------------
// GATConv fused pipeline, round 11:
//   1. k_zero : clear degree histogram
//   2. k_cvt  : x -> fp16 g_xh ; W -> fp16 TRANSPOSED g_wt[768][64]
//   3. k_gemm : h = x@W (fp16 mma.m16n8k16), ONE block per 128 rows,
//               loop over all 12 heads (A tile loaded once); attn epilogue
//   4. k_hist / k_scan (single block) / k_scatter : CSR by dst
//   5. k_agg  : per-dst softmax (all-thread parallel) + fp16 gather +
//               head mean + residual relu
// Shapes: N=50000, C=64, H=12, E=400000 (+N self loops)
// ---------------------------------------------------------------------------

namespace {
constexpr int CD = 64;
constexpr int HN = 12;
constexpr int HC = 768;
constexpr int N_CAP = 50176;
constexpr int E_CAP = 460800;
constexpr int XPAD = 72;          // smem row stride in halves
}

__device__ __half2 g_h [(size_t)N_CAP * HC / 2];   // fp16 projected features
__device__ __half  g_xh[(size_t)N_CAP * CD];       // fp16 x
__device__ __half  g_wt[HC * CD];                  // fp16 W transposed [n][k]
__device__ float g_asrc [N_CAP * HN];
__device__ float g_adst [N_CAP * HN];
__device__ int   g_deg  [N_CAP];
__device__ int   g_off  [N_CAP];
__device__ int   g_pos  [N_CAP];
__device__ int   g_csr  [E_CAP];

__device__ __forceinline__ void mma_f16(float d[4], unsigned a0, unsigned a1,
                                        unsigned a2, unsigned a3,
                                        unsigned b0, unsigned b1) {
    asm volatile(
        "mma.sync.aligned.m16n8k16.row.col.f32.f16.f16.f32 "
        "{%0,%1,%2,%3},{%4,%5,%6,%7},{%8,%9},{%0,%1,%2,%3};"
        : "+f"(d[0]), "+f"(d[1]), "+f"(d[2]), "+f"(d[3])
        : "r"(a0), "r"(a1), "r"(a2), "r"(a3), "r"(b0), "r"(b1));
}

// ---------------------------------------------------------------------------
__global__ void k_zero(int N) {
    int i = blockIdx.x * blockDim.x + threadIdx.x;
    if (i < N) g_deg[i] = 0;
}

// ---------------------------------------------------------------------------
// Convert x to fp16 and W to fp16 transposed.
__global__ void k_cvt(const float* __restrict__ x, const float* __restrict__ Wm,
                      int N) {
    int i = blockIdx.x * blockDim.x + threadIdx.x;
    int nx4 = N * 16;
    if (i < nx4) {
        float4 v = __ldg((const float4*)x + i);
        __align__(8) __half2 hb[2];
        hb[0] = __floats2half2_rn(v.x, v.y);
        hb[1] = __floats2half2_rn(v.z, v.w);
        ((uint2*)g_xh)[i] = *(const uint2*)hb;
    }
    if (i < 64 * (HC / 4)) {                  // W: 64 x 768 floats
        int k = i / (HC / 4), c4 = i % (HC / 4);
        float4 wv = __ldg((const float4*)Wm + i);
        int n0 = c4 * 4;
        g_wt[(n0 + 0) * CD + k] = __float2half_rn(wv.x);
        g_wt[(n0 + 1) * CD + k] = __float2half_rn(wv.y);
        g_wt[(n0 + 2) * CD + k] = __float2half_rn(wv.z);
        g_wt[(n0 + 3) * CD + k] = __float2half_rn(wv.w);
    }
}

// ---------------------------------------------------------------------------
// GEMM: one block per 128 rows, loops over all 12 heads. 256 threads =
// 8 warps (4m x 2n), warp tile 32x32, mma m16n8k16, K=64 resident.
__global__ void __launch_bounds__(256) k_gemm(
    const float* __restrict__ att_src, const float* __restrict__ att_dst,
    int N) {
    __shared__ __half xs[128][XPAD];   // A tile (persistent across heads)
    __shared__ __half ws[64][XPAD];    // B tile, transposed [n][k]
    __shared__ __half ds[128][XPAD];   // D stage
    int t = threadIdx.x;
    int brow = blockIdx.x * 128;

    // fill A once: pure fp16 copy
#pragma unroll
    for (int i = 0; i < 4; i++) {
        int v = i * 256 + t;              // uint4 id in 128x64 halves
        int r = v >> 3, q = v & 7;
        int gr = brow + r;
        uint4 val = (gr < N) ? *(const uint4*)&g_xh[(size_t)gr * CD + q * 8]
                             : make_uint4(0u, 0u, 0u, 0u);
        *(uint4*)&xs[r][q * 8] = val;
    }

    int warp = t >> 5, lane = t & 31;
    int wm = warp >> 1;               // 0..3
    int wn = warp & 1;                // 0..1
    int gp = lane >> 2, ctid = lane & 3;

    for (int head = 0; head < HN; head++) {
        __syncthreads();              // prior epilogue reads done
        // fill B for this head: pure fp16 copy
#pragma unroll
        for (int i = 0; i < 2; i++) {
            int v = i * 256 + t;          // uint4 id in 64x64 halves
            int n = v >> 3, q = v & 7;
            *(uint4*)&ws[n][q * 8] =
                *(const uint4*)&g_wt[(head * 64 + n) * CD + q * 8];
        }
        __syncthreads();

        float c[2][4][4] = {};
#pragma unroll
        for (int ks = 0; ks < 4; ks++) {
            int k0 = ks * 16;
            unsigned a[2][4], b[4][2];
#pragma unroll
            for (int mt = 0; mt < 2; mt++) {
                int r = wm * 32 + mt * 16 + gp;
                a[mt][0] = *(const unsigned*)&xs[r][k0 + ctid * 2];
                a[mt][1] = *(const unsigned*)&xs[r + 8][k0 + ctid * 2];
                a[mt][2] = *(const unsigned*)&xs[r][k0 + ctid * 2 + 8];
                a[mt][3] = *(const unsigned*)&xs[r + 8][k0 + ctid * 2 + 8];
            }
#pragma unroll
            for (int nt = 0; nt < 4; nt++) {
                int n = wn * 32 + nt * 8 + gp;
                b[nt][0] = *(const unsigned*)&ws[n][k0 + ctid * 2];
                b[nt][1] = *(const unsigned*)&ws[n][k0 + ctid * 2 + 8];
            }
#pragma unroll
            for (int mt = 0; mt < 2; mt++)
#pragma unroll
                for (int nt = 0; nt < 4; nt++)
                    mma_f16(c[mt][nt], a[mt][0], a[mt][1], a[mt][2], a[mt][3],
                            b[nt][0], b[nt][1]);
        }

        // stage D (fp16)
#pragma unroll
        for (int mt = 0; mt < 2; mt++)
#pragma unroll
            for (int nt = 0; nt < 4; nt++) {
                int r = wm * 32 + mt * 16 + gp;
                int col = wn * 32 + nt * 8 + ctid * 2;
                *(__half2*)&ds[r][col] =
                    __floats2half2_rn(c[mt][nt][0], c[mt][nt][1]);
                *(__half2*)&ds[r + 8][col] =
                    __floats2half2_rn(c[mt][nt][2], c[mt][nt][3]);
            }
        __syncthreads();

        // epilogue: 2 threads per row, 32 halves each
        {
            int r = t >> 1, half0 = (t & 1) * 32;
            int gr = brow + r;
            __align__(16) __half hbuf[32];
#pragma unroll
            for (int j = 0; j < 4; j++)
                ((uint4*)hbuf)[j] = *(const uint4*)&ds[r][half0 + j * 8];

            float ps = 0.f, pd = 0.f;
#pragma unroll
            for (int j = 0; j < 8; j++) {
                float4 as = __ldg((const float4*)att_src + head * 16 + (half0 >> 2) + j);
                float4 ad = __ldg((const float4*)att_dst + head * 16 + (half0 >> 2) + j);
                float f0 = __half2float(hbuf[j * 4 + 0]);
                float f1 = __half2float(hbuf[j * 4 + 1]);
                float f2 = __half2float(hbuf[j * 4 + 2]);
                float f3 = __half2float(hbuf[j * 4 + 3]);
                ps += f0 * as.x + f1 * as.y + f2 * as.z + f3 * as.w;
                pd += f0 * ad.x + f1 * ad.y + f2 * ad.z + f3 * ad.w;
            }
            ps += __shfl_xor_sync(0xffffffffu, ps, 1);
            pd += __shfl_xor_sync(0xffffffffu, pd, 1);

            if (gr < N) {
                uint4* dst = (uint4*)&g_h[((size_t)gr * HC + head * 64 + half0) / 2];
#pragma unroll
                for (int j = 0; j < 4; j++) dst[j] = ((const uint4*)hbuf)[j];
                if ((t & 1) == 0) {
                    g_asrc[gr * HN + head] = ps;
                    g_adst[gr * HN + head] = pd;
                }
            }
        }
    }
}

// ---------------------------------------------------------------------------
__global__ void k_hist(const int* __restrict__ ei, int E, int Etot) {
    int e = blockIdx.x * blockDim.x + threadIdx.x;
    if (e >= Etot) return;
    int d = (e < E) ? ei[E + e] : (e - E);
    atomicAdd(&g_deg[d], 1);
}

// single-block exclusive scan of g_deg -> g_off / g_pos
__global__ void k_scan(int N) {
    __shared__ int sm[1024];
    int t = threadIdx.x;
    int chunk = (N + 1023) / 1024;
    int lo = t * chunk, hi = min(lo + chunk, N);
    int s = 0;
    for (int i = lo; i < hi; i++) s += g_deg[i];
    sm[t] = s;
    __syncthreads();
#pragma unroll
    for (int o = 1; o < 1024; o <<= 1) {
        int v = (t >= o) ? sm[t - o] : 0;
        __syncthreads();
        sm[t] += v;
        __syncthreads();
    }
    int run = sm[t] - s;     // exclusive prefix
    for (int i = lo; i < hi; i++) {
        g_off[i] = run;
        g_pos[i] = run;
        run += g_deg[i];
    }
}

__global__ void k_scatter(const int* __restrict__ ei, int E, int Etot) {
    int e = blockIdx.x * blockDim.x + threadIdx.x;
    if (e >= Etot) return;
    int s, d;
    if (e < E) { s = ei[e]; d = ei[E + e]; }
    else       { s = d = e - E; }
    int p = atomicAdd(&g_pos[d], 1);
    g_csr[p] = s;
}

// ---------------------------------------------------------------------------
// Fused per-dst: softmax (all 192 threads: 16-lane group per head) +
// weighted fp16 gather + head mean + residual relu.
__global__ void __launch_bounds__(192) k_agg(
    const float* __restrict__ x, const float* __restrict__ bias,
    float* __restrict__ y, int N) {
    __shared__ float4 s_red[192];

    int i = blockIdx.x;
    int tid = threadIdx.x;
    int off = g_off[i];
    int deg = g_deg[i];
    int end = off + deg;
    int h = tid >> 4;          // head 0..11
    int c4 = tid & 15;         // 4-float chunk within head channels
    int sub = c4;              // lane-in-group for softmax phase

    float ad = g_adst[i * HN + h];

    // --- softmax stats: each 16-lane group handles its head, stride 16 ---
    float mx = -3.4e38f;
    for (int e = off + sub; e < end; e += 16) {
        float v = g_asrc[g_csr[e] * HN + h] + ad;
        v = (v > 0.f) ? v : 0.2f * v;
        mx = fmaxf(mx, v);
    }
#pragma unroll
    for (int o = 8; o; o >>= 1)
        mx = fmaxf(mx, __shfl_xor_sync(0xffffffffu, mx, o));

    float sum = 0.f;
    for (int e = off + sub; e < end; e += 16) {
        float v = g_asrc[g_csr[e] * HN + h] + ad;
        v = (v > 0.f) ? v : 0.2f * v;
        sum += __expf(v - mx);
    }
#pragma unroll
    for (int o = 8; o; o >>= 1)
        sum += __shfl_xor_sync(0xffffffffu, sum, o);

    // --- weighted gather (2-way unrolled) ---
    float4 acc = make_float4(0.f, 0.f, 0.f, 0.f);
    int e = off;
    for (; e + 1 < end; e += 2) {
        int s0 = g_csr[e], s1 = g_csr[e + 1];
        float v0 = g_asrc[s0 * HN + h] + ad;
        float v1 = g_asrc[s1 * HN + h] + ad;
        v0 = (v0 > 0.f) ? v0 : 0.2f * v0;
        v1 = (v1 > 0.f) ? v1 : 0.2f * v1;
        float w0 = __expf(v0 - mx);
        float w1 = __expf(v1 - mx);
        uint2 p0 = *(const uint2*)&g_h[(size_t)s0 * (HC / 2) + h * (CD / 2) + c4 * 2];
        uint2 p1 = *(const uint2*)&g_h[(size_t)s1 * (HC / 2) + h * (CD / 2) + c4 * 2];
        float2 a0 = __half22float2(*reinterpret_cast<const __half2*>(&p0.x));
        float2 a1 = __half22float2(*reinterpret_cast<const __half2*>(&p0.y));
        float2 b0 = __half22float2(*reinterpret_cast<const __half2*>(&p1.x));
        float2 b1 = __half22float2(*reinterpret_cast<const __half2*>(&p1.y));
        acc.x += w0 * a0.x + w1 * b0.x;
        acc.y += w0 * a0.y + w1 * b0.y;
        acc.z += w0 * a1.x + w1 * b1.x;
        acc.w += w0 * a1.y + w1 * b1.y;
    }
    if (e < end) {
        int s0 = g_csr[e];
        float v0 = g_asrc[s0 * HN + h] + ad;
        v0 = (v0 > 0.f) ? v0 : 0.2f * v0;
        float w0 = __expf(v0 - mx);
        uint2 p0 = *(const uint2*)&g_h[(size_t)s0 * (HC / 2) + h * (CD / 2) + c4 * 2];
        float2 a0 = __half22float2(*reinterpret_cast<const __half2*>(&p0.x));
        float2 a1 = __half22float2(*reinterpret_cast<const __half2*>(&p0.y));
        acc.x += w0 * a0.x; acc.y += w0 * a0.y;
        acc.z += w0 * a1.x; acc.w += w0 * a1.y;
    }

    float inv = 1.f / (sum + 1e-16f);
    acc.x *= inv; acc.y *= inv; acc.z *= inv; acc.w *= inv;
    s_red[tid] = acc;
    __syncthreads();

    if (tid < 16) {
        float4 s4 = make_float4(0.f, 0.f, 0.f, 0.f);
#pragma unroll
        for (int hh = 0; hh < HN; hh++) {
            float4 v = s_red[hh * 16 + tid];
            s4.x += v.x; s4.y += v.y; s4.z += v.z; s4.w += v.w;
        }
        const float invH = 1.0f / (float)HN;
        float4 xv = __ldg((const float4*)x + (size_t)i * 16 + tid);
        float4 bv = __ldg((const float4*)bias + tid);
        float4 r;
        r.x = fmaxf(xv.x + s4.x * invH + bv.x, 0.f);
        r.y = fmaxf(xv.y + s4.y * invH + bv.y, 0.f);
        r.z = fmaxf(xv.z + s4.z * invH + bv.z, 0.f);
        r.w = fmaxf(xv.w + s4.w * invH + bv.w, 0.f);
        ((float4*)y)[(size_t)i * 16 + tid] = r;
    }
}

// ---------------------------------------------------------------------------
extern "C" void kernel_launch(void* const* d_in, const int* in_sizes, int n_in,
                              void* d_out, int out_size) {
    (void)n_in; (void)out_size;
    const float* x    = (const float*)d_in[0];
    const int*   ei   = (const int*)d_in[1];
    const float* Wm   = (const float*)d_in[2];
    const float* a_s  = (const float*)d_in[3];
    const float* a_d  = (const float*)d_in[4];
    const float* bias = (const float*)d_in[5];

    int N = in_sizes[0] / CD;
    int E = in_sizes[1] / 2;
    if (N > N_CAP) N = N_CAP;
    if (E + N > E_CAP) E = E_CAP - N;
    int Etot = E + N;

    k_zero<<<(N + 255) / 256, 256>>>(N);

    int ncvt = N * 16;                     // covers both x and W ranges
    k_cvt<<<(ncvt + 255) / 256, 256>>>(x, Wm, N);

    k_gemm<<<(N + 127) / 128, 256>>>(a_s, a_d, N);

    k_hist<<<(Etot + 255) / 256, 256>>>(ei, E, Etot);
    k_scan<<<1, 1024>>>(N);
    k_scatter<<<(Etot + 255) / 256, 256>>>(ei, E, Etot);

    k_agg<<<N, 192>>>(x, bias, (float*)d_out, N);
}